// round 4
// baseline (speedup 1.0000x reference)
#include <cuda_runtime.h>

// Swin-style window attention, fully fused per 8x8 window.
// B=4, H=W=256, C=192, NH=6, hd=32, WS=8 -> 4096 windows, 64 tokens each.
// One CTA of 256 threads per window; everything staged in shared memory; fp32.

#define BATCH 4
#define IMGH  256
#define IMGW  256
#define CH    192
#define NHEAD 6
#define HDIM  32
#define TOK   64

#define XS 196   // stride of 64x192 tiles (x, attn_out, weight staging)
#define QS 36    // stride of q / v [64][32] tiles
#define KS 68    // stride of k-transposed [32][64] tile
#define PS 68    // stride of scores [64][64] tile
#define OS 100   // stride of proj output staging [64][96]

// floats: sx 12544 + sout 12544 + sw 18816 + sq 2304 + skt 2176 + sv 2304 + sp 4352 + sb 96
#define SMEM_FLOATS (64*XS + 64*XS + 96*XS + 64*QS + 32*KS + 64*QS + 64*PS + 96)
#define SMEM_BYTES  (SMEM_FLOATS * 4)

__global__ __launch_bounds__(256, 1)
void win_attn_kernel(const float* __restrict__ x,
                     const float* __restrict__ qkv_w,   // [576,192]
                     const float* __restrict__ qkv_b,   // [576]
                     const float* __restrict__ proj_w,  // [192,192]
                     const float* __restrict__ proj_b,  // [192]
                     const float* __restrict__ bias,    // [6,64,64]
                     float* __restrict__ out)
{
    extern __shared__ float sm[];
    float* sx   = sm;                // 64 x XS : input window tile
    float* sout = sx   + 64*XS;      // 64 x XS : per-head attention output accumulator
    float* sw   = sout + 64*XS;      // 96 x XS : weight staging
    float* sq   = sw   + 96*XS;      // 64 x QS : q (pre-scaled)
    float* skt  = sq   + 64*QS;      // 32 x KS : k transposed [d][t]
    float* sv   = skt  + 32*KS;      // 64 x QS : v
    float* sp   = sv   + 64*QS;      // 64 x PS : scores / probabilities
    float* sb   = sp   + 64*PS;      // 96     : bias staging
    float* pout = sq;                // 64 x OS : proj staging, reuses sq..sp (6400 <= 11136)

    const int tid = threadIdx.x;
    const int w   = blockIdx.x;
    const int b   = w >> 10;
    const int wh  = (w >> 5) & 31;
    const int ww  = w & 31;

    // base element offset of token 0 of this window in x/out [B, H*W, C]
    const long long base = ((long long)b * (IMGH*IMGW) + (long long)(wh*8)*IMGW + (ww*8)) * CH;
    // token t (0..63) offset from base: (t/8)*IMGW*CH + (t%8)*CH

    // ---- gather x window tile: 64 tokens x 192 ch (48 float4 per token) ----
    for (int i = tid; i < 64*48; i += 256) {
        const int t  = i / 48;
        const int c4 = i % 48;
        const long long g = base + (long long)(t >> 3) * (IMGW*CH) + (t & 7) * CH + c4*4;
        *(float4*)(sx + t*XS + c4*4) = *(const float4*)(x + g);
    }
    __syncthreads();

    const float scale = 0.17677669529663687f; // 1/sqrt(32)

    for (int h = 0; h < NHEAD; ++h) {
        // ---- stage 96 qkv weight rows (q:0..31, k:32..63, v:64..95) + biases ----
        for (int i = tid; i < 96*48; i += 256) {
            const int r  = i / 48;
            const int c4 = i % 48;
            const int src = (r < 32) ? (h*HDIM + r)
                          : (r < 64) ? (CH + h*HDIM + (r - 32))
                                     : (2*CH + h*HDIM + (r - 64));
            *(float4*)(sw + r*XS + c4*4) = *(const float4*)(qkv_w + src*CH + c4*4);
        }
        if (tid < 96) {
            const int r = tid;
            const int src = (r < 32) ? (h*HDIM + r)
                          : (r < 64) ? (CH + h*HDIM + (r - 32))
                                     : (2*CH + h*HDIM + (r - 64));
            sb[r] = qkv_b[src];
        }
        __syncthreads();

        // ---- GEMM1: qkv_head[64][96] = sx[64][192] @ sw[96][192]^T  (+bias) ----
        {
            const int ty = tid >> 4;       // 0..15
            const int tx = tid & 15;       // 0..15
            const int m0 = ty * 4;
            float acc[4][6];
            #pragma unroll
            for (int i = 0; i < 4; ++i)
                #pragma unroll
                for (int j = 0; j < 6; ++j) acc[i][j] = 0.f;

            #pragma unroll 4
            for (int k = 0; k < CH; k += 4) {
                float4 a[4], bb[6];
                #pragma unroll
                for (int i = 0; i < 4; ++i) a[i] = *(const float4*)(sx + (m0+i)*XS + k);
                #pragma unroll
                for (int j = 0; j < 6; ++j) bb[j] = *(const float4*)(sw + (tx + 16*j)*XS + k);
                #pragma unroll
                for (int i = 0; i < 4; ++i)
                    #pragma unroll
                    for (int j = 0; j < 6; ++j)
                        acc[i][j] += a[i].x*bb[j].x + a[i].y*bb[j].y
                                   + a[i].z*bb[j].z + a[i].w*bb[j].w;
            }

            #pragma unroll
            for (int j = 0; j < 6; ++j) {
                const int n = tx + 16*j;
                const float bv = sb[n];
                #pragma unroll
                for (int i = 0; i < 4; ++i) {
                    const int m = m0 + i;
                    const float v = acc[i][j] + bv;
                    if (j < 2)       sq[m*QS + n]          = v * scale;  // q, pre-scaled
                    else if (j < 4)  skt[(n-32)*KS + m]    = v;          // k transposed
                    else             sv[m*QS + (n-64)]     = v;          // v
                }
            }
        }
        __syncthreads();

        // ---- GEMM2: scores[64][64] = q @ k^T + bias[h] ----
        {
            const int ty = tid >> 4;
            const int tx = tid & 15;
            const int m0 = ty * 4;
            const int n0 = tx * 4;
            float acc[4][4];
            #pragma unroll
            for (int i = 0; i < 4; ++i)
                #pragma unroll
                for (int j = 0; j < 4; ++j) acc[i][j] = 0.f;

            #pragma unroll
            for (int k = 0; k < HDIM; k += 4) {
                float4 a[4], bb[4];
                #pragma unroll
                for (int i = 0; i < 4; ++i) a[i] = *(const float4*)(sq + (m0+i)*QS + k);
                #pragma unroll
                for (int kk = 0; kk < 4; ++kk) bb[kk] = *(const float4*)(skt + (k+kk)*KS + n0);
                #pragma unroll
                for (int i = 0; i < 4; ++i) {
                    const float* af = (const float*)&a[i];
                    #pragma unroll
                    for (int kk = 0; kk < 4; ++kk) {
                        const float* bf = (const float*)&bb[kk];
                        #pragma unroll
                        for (int j = 0; j < 4; ++j) acc[i][j] += af[kk] * bf[j];
                    }
                }
            }
            #pragma unroll
            for (int i = 0; i < 4; ++i) {
                const int m = m0 + i;
                const float4 bi = *(const float4*)(bias + ((h*64 + m) << 6) + n0);
                float4 s4;
                s4.x = acc[i][0] + bi.x;
                s4.y = acc[i][1] + bi.y;
                s4.z = acc[i][2] + bi.z;
                s4.w = acc[i][3] + bi.w;
                *(float4*)(sp + m*PS + n0) = s4;
            }
        }
        __syncthreads();

        // ---- softmax over rows of sp (4 lanes per row) ----
        {
            const int r    = tid >> 2;
            const int part = tid & 3;
            float* row = sp + r*PS + part*16;
            float mx = -1e30f;
            #pragma unroll
            for (int j = 0; j < 16; ++j) mx = fmaxf(mx, row[j]);
            mx = fmaxf(mx, __shfl_xor_sync(0xffffffffu, mx, 1));
            mx = fmaxf(mx, __shfl_xor_sync(0xffffffffu, mx, 2));
            float s = 0.f;
            #pragma unroll
            for (int j = 0; j < 16; ++j) { float e = __expf(row[j] - mx); row[j] = e; s += e; }
            s += __shfl_xor_sync(0xffffffffu, s, 1);
            s += __shfl_xor_sync(0xffffffffu, s, 2);
            const float inv = 1.0f / s;
            #pragma unroll
            for (int j = 0; j < 16; ++j) row[j] *= inv;
        }
        __syncthreads();

        // ---- GEMM3: out_h[64][32] = P[64][64] @ v[64][32] ----
        {
            const int ty = tid >> 3;   // 0..31
            const int tx = tid & 7;    // 0..7
            const int m0 = ty * 2;
            const int n0 = tx * 4;
            float acc[2][4];
            #pragma unroll
            for (int i = 0; i < 2; ++i)
                #pragma unroll
                for (int j = 0; j < 4; ++j) acc[i][j] = 0.f;

            #pragma unroll 4
            for (int k = 0; k < 64; k += 4) {
                float4 a[2], bb[4];
                #pragma unroll
                for (int i = 0; i < 2; ++i) a[i] = *(const float4*)(sp + (m0+i)*PS + k);
                #pragma unroll
                for (int kk = 0; kk < 4; ++kk) bb[kk] = *(const float4*)(sv + (k+kk)*QS + n0);
                #pragma unroll
                for (int i = 0; i < 2; ++i) {
                    const float* af = (const float*)&a[i];
                    #pragma unroll
                    for (int kk = 0; kk < 4; ++kk) {
                        const float* bf = (const float*)&bb[kk];
                        #pragma unroll
                        for (int j = 0; j < 4; ++j) acc[i][j] += af[kk] * bf[j];
                    }
                }
            }
            #pragma unroll
            for (int i = 0; i < 2; ++i) {
                float4 v4;
                v4.x = acc[i][0]; v4.y = acc[i][1]; v4.z = acc[i][2]; v4.w = acc[i][3];
                *(float4*)(sout + (m0+i)*XS + h*HDIM + n0) = v4;
            }
        }
        __syncthreads();
    }

    // ---- projection: out[64][192] = sout[64][192] @ proj_w[192][192]^T + proj_b ----
    for (int chunk = 0; chunk < 2; ++chunk) {
        for (int i = tid; i < 96*48; i += 256) {
            const int r  = i / 48;
            const int c4 = i % 48;
            *(float4*)(sw + r*XS + c4*4) = *(const float4*)(proj_w + (chunk*96 + r)*CH + c4*4);
        }
        if (tid < 96) sb[tid] = proj_b[chunk*96 + tid];
        __syncthreads();

        {
            const int ty = tid >> 4;
            const int tx = tid & 15;
            const int m0 = ty * 4;
            float acc[4][6];
            #pragma unroll
            for (int i = 0; i < 4; ++i)
                #pragma unroll
                for (int j = 0; j < 6; ++j) acc[i][j] = 0.f;

            #pragma unroll 4
            for (int k = 0; k < CH; k += 4) {
                float4 a[4], bb[6];
                #pragma unroll
                for (int i = 0; i < 4; ++i) a[i] = *(const float4*)(sout + (m0+i)*XS + k);
                #pragma unroll
                for (int j = 0; j < 6; ++j) bb[j] = *(const float4*)(sw + (tx + 16*j)*XS + k);
                #pragma unroll
                for (int i = 0; i < 4; ++i)
                    #pragma unroll
                    for (int j = 0; j < 6; ++j)
                        acc[i][j] += a[i].x*bb[j].x + a[i].y*bb[j].y
                                   + a[i].z*bb[j].z + a[i].w*bb[j].w;
            }
            #pragma unroll
            for (int j = 0; j < 6; ++j) {
                const int n = tx + 16*j;
                const float bv = sb[n];
                #pragma unroll
                for (int i = 0; i < 4; ++i)
                    pout[(m0+i)*OS + n] = acc[i][j] + bv;
            }
        }
        __syncthreads();

        // coalesced scatter back to global (24 float4 per token per chunk)
        for (int i = tid; i < 64*24; i += 256) {
            const int t  = i / 24;
            const int c4 = i % 24;
            const long long g = base + (long long)(t >> 3) * (IMGW*CH) + (t & 7) * CH
                              + chunk*96 + c4*4;
            *(float4*)(out + g) = *(const float4*)(pout + t*OS + c4*4);
        }
        __syncthreads();
    }
}

extern "C" void kernel_launch(void* const* d_in, const int* in_sizes, int n_in,
                              void* d_out, int out_size)
{
    const float* x      = (const float*)d_in[0];
    const float* qkv_w  = (const float*)d_in[1];
    const float* qkv_b  = (const float*)d_in[2];
    const float* proj_w = (const float*)d_in[3];
    const float* proj_b = (const float*)d_in[4];
    const float* bias   = (const float*)d_in[5];
    float* out = (float*)d_out;

    cudaFuncSetAttribute(win_attn_kernel,
                         cudaFuncAttributeMaxDynamicSharedMemorySize, SMEM_BYTES);

    const int n_windows = BATCH * (IMGH/8) * (IMGW/8);   // 4096
    win_attn_kernel<<<n_windows, 256, SMEM_BYTES>>>(x, qkv_w, qkv_b, proj_w, proj_b, bias, out);
}

// round 6
// speedup vs baseline: 1.0028x; 1.0028x over previous
#include <cuda_runtime.h>

// Swin-style window attention, fully fused per 8x8 window.
// B=4, H=W=256, C=192, NH=6, hd=32, WS=8 -> 4096 windows, 64 tokens each.
// One CTA of 256 threads per window; everything staged in shared memory; fp32.

#define BATCH 4
#define IMGH  256
#define IMGW  256
#define CH    192
#define NHEAD 6
#define HDIM  32
#define TOK   64

#define XS 196   // stride of 64x192 tiles (x, attn_out, weight staging)
#define QS 36    // stride of q / v [64][32] tiles
#define KS 68    // stride of k-transposed [32][64] tile
#define PS 68    // stride of scores [64][64] tile
#define OS 100   // stride of proj output staging [64][96]

// floats: sx 12544 + sout 12544 + sw 18816 + sq 2304 + skt 2176 + sv 2304 + sp 4352 + sb 96
#define SMEM_FLOATS (64*XS + 64*XS + 96*XS + 64*QS + 32*KS + 64*QS + 64*PS + 96)
#define SMEM_BYTES  (SMEM_FLOATS * 4)

__global__ __launch_bounds__(256, 1)
void win_attn_kernel(const float* __restrict__ x,
                     const float* __restrict__ qkv_w,   // [576,192]
                     const float* __restrict__ qkv_b,   // [576]
                     const float* __restrict__ proj_w,  // [192,192]
                     const float* __restrict__ proj_b,  // [192]
                     const float* __restrict__ bias,    // [6,64,64]
                     float* __restrict__ out)
{
    extern __shared__ float sm[];
    float* sx   = sm;                // 64 x XS : input window tile
    float* sout = sx   + 64*XS;      // 64 x XS : per-head attention output accumulator
    float* sw   = sout + 64*XS;      // 96 x XS : weight staging
    float* sq   = sw   + 96*XS;      // 64 x QS : q (pre-scaled)
    float* skt  = sq   + 64*QS;      // 32 x KS : k transposed [d][t]
    float* sv   = skt  + 32*KS;      // 64 x QS : v
    float* sp   = sv   + 64*QS;      // 64 x PS : scores / probabilities
    float* sb   = sp   + 64*PS;      // 96     : bias staging
    float* pout = sq;                // 64 x OS : proj staging, reuses sq..sp (6400 <= 11136)

    const int tid = threadIdx.x;
    const int w   = blockIdx.x;
    const int b   = w >> 10;
    const int wh  = (w >> 5) & 31;
    const int ww  = w & 31;

    // base element offset of token 0 of this window in x/out [B, H*W, C]
    const long long base = ((long long)b * (IMGH*IMGW) + (long long)(wh*8)*IMGW + (ww*8)) * CH;
    // token t (0..63) offset from base: (t/8)*IMGW*CH + (t%8)*CH

    // ---- gather x window tile: 64 tokens x 192 ch (48 float4 per token) ----
    for (int i = tid; i < 64*48; i += 256) {
        const int t  = i / 48;
        const int c4 = i % 48;
        const long long g = base + (long long)(t >> 3) * (IMGW*CH) + (t & 7) * CH + c4*4;
        *(float4*)(sx + t*XS + c4*4) = *(const float4*)(x + g);
    }
    __syncthreads();

    const float scale = 0.17677669529663687f; // 1/sqrt(32)

    for (int h = 0; h < NHEAD; ++h) {
        // ---- stage 96 qkv weight rows (q:0..31, k:32..63, v:64..95) + biases ----
        for (int i = tid; i < 96*48; i += 256) {
            const int r  = i / 48;
            const int c4 = i % 48;
            const int src = (r < 32) ? (h*HDIM + r)
                          : (r < 64) ? (CH + h*HDIM + (r - 32))
                                     : (2*CH + h*HDIM + (r - 64));
            *(float4*)(sw + r*XS + c4*4) = *(const float4*)(qkv_w + src*CH + c4*4);
        }
        if (tid < 96) {
            const int r = tid;
            const int src = (r < 32) ? (h*HDIM + r)
                          : (r < 64) ? (CH + h*HDIM + (r - 32))
                                     : (2*CH + h*HDIM + (r - 64));
            sb[r] = qkv_b[src];
        }
        __syncthreads();

        // ---- GEMM1: qkv_head[64][96] = sx[64][192] @ sw[96][192]^T  (+bias) ----
        {
            const int ty = tid >> 4;       // 0..15
            const int tx = tid & 15;       // 0..15
            const int m0 = ty * 4;
            float acc[4][6];
            #pragma unroll
            for (int i = 0; i < 4; ++i)
                #pragma unroll
                for (int j = 0; j < 6; ++j) acc[i][j] = 0.f;

            #pragma unroll 4
            for (int k = 0; k < CH; k += 4) {
                float4 a[4], bb[6];
                #pragma unroll
                for (int i = 0; i < 4; ++i) a[i] = *(const float4*)(sx + (m0+i)*XS + k);
                #pragma unroll
                for (int j = 0; j < 6; ++j) bb[j] = *(const float4*)(sw + (tx + 16*j)*XS + k);
                #pragma unroll
                for (int i = 0; i < 4; ++i)
                    #pragma unroll
                    for (int j = 0; j < 6; ++j)
                        acc[i][j] += a[i].x*bb[j].x + a[i].y*bb[j].y
                                   + a[i].z*bb[j].z + a[i].w*bb[j].w;
            }

            #pragma unroll
            for (int j = 0; j < 6; ++j) {
                const int n = tx + 16*j;
                const float bv = sb[n];
                #pragma unroll
                for (int i = 0; i < 4; ++i) {
                    const int m = m0 + i;
                    const float v = acc[i][j] + bv;
                    if (j < 2)       sq[m*QS + n]          = v * scale;  // q, pre-scaled
                    else if (j < 4)  skt[(n-32)*KS + m]    = v;          // k transposed
                    else             sv[m*QS + (n-64)]     = v;          // v
                }
            }
        }
        __syncthreads();

        // ---- GEMM2: scores[64][64] = q @ k^T + bias[h] ----
        {
            const int ty = tid >> 4;
            const int tx = tid & 15;
            const int m0 = ty * 4;
            const int n0 = tx * 4;
            float acc[4][4];
            #pragma unroll
            for (int i = 0; i < 4; ++i)
                #pragma unroll
                for (int j = 0; j < 4; ++j) acc[i][j] = 0.f;

            #pragma unroll
            for (int k = 0; k < HDIM; k += 4) {
                float4 a[4], bb[4];
                #pragma unroll
                for (int i = 0; i < 4; ++i) a[i] = *(const float4*)(sq + (m0+i)*QS + k);
                #pragma unroll
                for (int kk = 0; kk < 4; ++kk) bb[kk] = *(const float4*)(skt + (k+kk)*KS + n0);
                #pragma unroll
                for (int i = 0; i < 4; ++i) {
                    const float* af = (const float*)&a[i];
                    #pragma unroll
                    for (int kk = 0; kk < 4; ++kk) {
                        const float* bf = (const float*)&bb[kk];
                        #pragma unroll
                        for (int j = 0; j < 4; ++j) acc[i][j] += af[kk] * bf[j];
                    }
                }
            }
            #pragma unroll
            for (int i = 0; i < 4; ++i) {
                const int m = m0 + i;
                const float4 bi = *(const float4*)(bias + ((h*64 + m) << 6) + n0);
                float4 s4;
                s4.x = acc[i][0] + bi.x;
                s4.y = acc[i][1] + bi.y;
                s4.z = acc[i][2] + bi.z;
                s4.w = acc[i][3] + bi.w;
                *(float4*)(sp + m*PS + n0) = s4;
            }
        }
        __syncthreads();

        // ---- softmax over rows of sp (4 lanes per row) ----
        {
            const int r    = tid >> 2;
            const int part = tid & 3;
            float* row = sp + r*PS + part*16;
            float mx = -1e30f;
            #pragma unroll
            for (int j = 0; j < 16; ++j) mx = fmaxf(mx, row[j]);
            mx = fmaxf(mx, __shfl_xor_sync(0xffffffffu, mx, 1));
            mx = fmaxf(mx, __shfl_xor_sync(0xffffffffu, mx, 2));
            float s = 0.f;
            #pragma unroll
            for (int j = 0; j < 16; ++j) { float e = __expf(row[j] - mx); row[j] = e; s += e; }
            s += __shfl_xor_sync(0xffffffffu, s, 1);
            s += __shfl_xor_sync(0xffffffffu, s, 2);
            const float inv = 1.0f / s;
            #pragma unroll
            for (int j = 0; j < 16; ++j) row[j] *= inv;
        }
        __syncthreads();

        // ---- GEMM3: out_h[64][32] = P[64][64] @ v[64][32] ----
        {
            const int ty = tid >> 3;   // 0..31
            const int tx = tid & 7;    // 0..7
            const int m0 = ty * 2;
            const int n0 = tx * 4;
            float acc[2][4];
            #pragma unroll
            for (int i = 0; i < 2; ++i)
                #pragma unroll
                for (int j = 0; j < 4; ++j) acc[i][j] = 0.f;

            #pragma unroll 4
            for (int k = 0; k < 64; k += 4) {
                float4 a[2], bb[4];
                #pragma unroll
                for (int i = 0; i < 2; ++i) a[i] = *(const float4*)(sp + (m0+i)*PS + k);
                #pragma unroll
                for (int kk = 0; kk < 4; ++kk) bb[kk] = *(const float4*)(sv + (k+kk)*QS + n0);
                #pragma unroll
                for (int i = 0; i < 2; ++i) {
                    const float* af = (const float*)&a[i];
                    #pragma unroll
                    for (int kk = 0; kk < 4; ++kk) {
                        const float* bf = (const float*)&bb[kk];
                        #pragma unroll
                        for (int j = 0; j < 4; ++j) acc[i][j] += af[kk] * bf[j];
                    }
                }
            }
            #pragma unroll
            for (int i = 0; i < 2; ++i) {
                float4 v4;
                v4.x = acc[i][0]; v4.y = acc[i][1]; v4.z = acc[i][2]; v4.w = acc[i][3];
                *(float4*)(sout + (m0+i)*XS + h*HDIM + n0) = v4;
            }
        }
        __syncthreads();
    }

    // ---- projection: out[64][192] = sout[64][192] @ proj_w[192][192]^T + proj_b ----
    for (int chunk = 0; chunk < 2; ++chunk) {
        for (int i = tid; i < 96*48; i += 256) {
            const int r  = i / 48;
            const int c4 = i % 48;
            *(float4*)(sw + r*XS + c4*4) = *(const float4*)(proj_w + (chunk*96 + r)*CH + c4*4);
        }
        if (tid < 96) sb[tid] = proj_b[chunk*96 + tid];
        __syncthreads();

        {
            const int ty = tid >> 4;
            const int tx = tid & 15;
            const int m0 = ty * 4;
            float acc[4][6];
            #pragma unroll
            for (int i = 0; i < 4; ++i)
                #pragma unroll
                for (int j = 0; j < 6; ++j) acc[i][j] = 0.f;

            #pragma unroll 4
            for (int k = 0; k < CH; k += 4) {
                float4 a[4], bb[6];
                #pragma unroll
                for (int i = 0; i < 4; ++i) a[i] = *(const float4*)(sout + (m0+i)*XS + k);
                #pragma unroll
                for (int j = 0; j < 6; ++j) bb[j] = *(const float4*)(sw + (tx + 16*j)*XS + k);
                #pragma unroll
                for (int i = 0; i < 4; ++i)
                    #pragma unroll
                    for (int j = 0; j < 6; ++j)
                        acc[i][j] += a[i].x*bb[j].x + a[i].y*bb[j].y
                                   + a[i].z*bb[j].z + a[i].w*bb[j].w;
            }
            #pragma unroll
            for (int j = 0; j < 6; ++j) {
                const int n = tx + 16*j;
                const float bv = sb[n];
                #pragma unroll
                for (int i = 0; i < 4; ++i)
                    pout[(m0+i)*OS + n] = acc[i][j] + bv;
            }
        }
        __syncthreads();

        // coalesced scatter back to global (24 float4 per token per chunk)
        for (int i = tid; i < 64*24; i += 256) {
            const int t  = i / 24;
            const int c4 = i % 24;
            const long long g = base + (long long)(t >> 3) * (IMGW*CH) + (t & 7) * CH
                              + chunk*96 + c4*4;
            *(float4*)(out + g) = *(const float4*)(pout + t*OS + c4*4);
        }
        __syncthreads();
    }
}

extern "C" void kernel_launch(void* const* d_in, const int* in_sizes, int n_in,
                              void* d_out, int out_size)
{
    const float* x      = (const float*)d_in[0];
    const float* qkv_w  = (const float*)d_in[1];
    const float* qkv_b  = (const float*)d_in[2];
    const float* proj_w = (const float*)d_in[3];
    const float* proj_b = (const float*)d_in[4];
    const float* bias   = (const float*)d_in[5];
    float* out = (float*)d_out;

    cudaFuncSetAttribute(win_attn_kernel,
                         cudaFuncAttributeMaxDynamicSharedMemorySize, SMEM_BYTES);

    const int n_windows = BATCH * (IMGH/8) * (IMGW/8);   // 4096
    win_attn_kernel<<<n_windows, 256, SMEM_BYTES>>>(x, qkv_w, qkv_b, proj_w, proj_b, bias, out);
}

// round 8
// speedup vs baseline: 1.3628x; 1.3591x over previous
#include <cuda_runtime.h>

// Swin-style window attention, fully fused per 8x8 window — tf32 tensor-core version.
// B=4, H=W=256, C=192, NH=6, hd=32, WS=8 -> 4096 windows, 64 tokens each.
// One CTA of 256 threads (8 warps) per window. All GEMMs via mma.sync m16n8k8 tf32,
// fp32 accumulate; softmax exact fp32. Operands rounded to tf32 (cvt.rna) when staged.

#define BATCH 4
#define IMGH  256
#define IMGW  256
#define CH    192
#define NHEAD 6
#define HDIM  32

#define XS  196   // stride of 64x192 tiles (sx, sout) and 96x192 weight tile
#define QSQ 36    // sq stride      (A-loads: bank 4*ln4+lc, conflict-free)
#define KS  72    // skt stride     (B-loads: bank 8*lc+ln4, conflict-free)
#define VS  40    // sv stride      (B-loads: bank 8*lc+ln4, conflict-free)
#define PS  68    // sp stride      (A-loads: bank 4*ln4+lc, conflict-free)
#define OS  100   // proj staging stride

// floats: sx 12544 + sout 12544 + sw 18816 + sq 2304 + skt 2304 + sv 2560 + sp 4352 + sb 96
#define SMEM_FLOATS (64*XS + 64*XS + 96*XS + 64*QSQ + 32*KS + 64*VS + 64*PS + 96)
#define SMEM_BYTES  (SMEM_FLOATS * 4)

__device__ __forceinline__ unsigned f2tf(float f) {
    unsigned u;
    asm("cvt.rna.tf32.f32 %0, %1;" : "=r"(u) : "f"(f));
    return u;
}
__device__ __forceinline__ float tfbits(float f) {       // round f to tf32, keep as float bits
    return __uint_as_float(f2tf(f));
}
__device__ __forceinline__ unsigned ldb(const float* p) { // load tf32 bits from smem
    return __float_as_uint(*p);
}
__device__ __forceinline__ void mma8(float* d, const unsigned* a, unsigned b0, unsigned b1) {
    asm volatile(
        "mma.sync.aligned.m16n8k8.row.col.f32.tf32.tf32.f32 "
        "{%0,%1,%2,%3}, {%4,%5,%6,%7}, {%8,%9}, {%0,%1,%2,%3};"
        : "+f"(d[0]), "+f"(d[1]), "+f"(d[2]), "+f"(d[3])
        : "r"(a[0]), "r"(a[1]), "r"(a[2]), "r"(a[3]), "r"(b0), "r"(b1));
}

__global__ __launch_bounds__(256, 1)
void win_attn_kernel(const float* __restrict__ x,
                     const float* __restrict__ qkv_w,   // [576,192]
                     const float* __restrict__ qkv_b,   // [576]
                     const float* __restrict__ proj_w,  // [192,192]
                     const float* __restrict__ proj_b,  // [192]
                     const float* __restrict__ bias,    // [6,64,64]
                     float* __restrict__ out)
{
    extern __shared__ float sm[];
    float* sx   = sm;                // 64 x XS  : input window tile (tf32)
    float* sout = sx   + 64*XS;      // 64 x XS  : attention output accumulator (tf32)
    float* sw   = sout + 64*XS;      // 96 x XS  : weight staging (tf32)
    float* sq   = sw   + 96*XS;      // 64 x QSQ : q, pre-scaled (tf32)
    float* skt  = sq   + 64*QSQ;     // 32 x KS  : k transposed [d][t] (tf32)
    float* sv   = skt  + 32*KS;      // 64 x VS  : v (tf32)
    float* sp   = sv   + 64*VS;      // 64 x PS  : bias -> scores -> probs
    float* sb   = sp   + 64*PS;      // 96       : fp32 bias staging
    float* pout = sq;                // 64 x OS  : proj staging (fp32), reuses sq..sp

    const int tid  = threadIdx.x;
    const int warp = tid >> 5;
    const int lane = tid & 31;
    const int ln4  = lane >> 2;      // 0..7  (row group)
    const int lc   = lane & 3;       // 0..3  (k / col group)

    const int w  = blockIdx.x;
    const int b  = w >> 10;
    const int wh = (w >> 5) & 31;
    const int ww = w & 31;
    const long long base = ((long long)b * (IMGH*IMGW) + (long long)(wh*8)*IMGW + (ww*8)) * CH;

    // ---- gather x window tile (convert to tf32) ----
    for (int i = tid; i < 64*48; i += 256) {
        const int t  = i / 48;
        const int c4 = i % 48;
        const long long g = base + (long long)(t >> 3) * (IMGW*CH) + (t & 7) * CH + c4*4;
        float4 v = *(const float4*)(x + g);
        float* d = sx + t*XS + c4*4;
        d[0] = tfbits(v.x); d[1] = tfbits(v.y); d[2] = tfbits(v.z); d[3] = tfbits(v.w);
    }
    __syncthreads();

    const float scale = 0.17677669529663687f; // 1/sqrt(32)

    for (int h = 0; h < NHEAD; ++h) {
        // ---- stage 96 qkv weight rows (q:0..31, k:32..63, v:64..95), biases, attn bias ----
        for (int i = tid; i < 96*48; i += 256) {
            const int r  = i / 48;
            const int c4 = i % 48;
            const int src = (r < 32) ? (h*HDIM + r)
                          : (r < 64) ? (CH + h*HDIM + (r - 32))
                                     : (2*CH + h*HDIM + (r - 64));
            float4 v = *(const float4*)(qkv_w + src*CH + c4*4);
            float* d = sw + r*XS + c4*4;
            d[0] = tfbits(v.x); d[1] = tfbits(v.y); d[2] = tfbits(v.z); d[3] = tfbits(v.w);
        }
        if (tid < 96) {
            const int r = tid;
            const int src = (r < 32) ? (h*HDIM + r)
                          : (r < 64) ? (CH + h*HDIM + (r - 32))
                                     : (2*CH + h*HDIM + (r - 64));
            sb[r] = qkv_b[src];
        }
        // stage attention bias[h] into sp (fp32) — GEMM2 accumulates onto it in place
        for (int i = tid; i < 64*16; i += 256) {
            const int m  = i >> 4;
            const int c4 = i & 15;
            *(float4*)(sp + m*PS + c4*4) = *(const float4*)(bias + h*4096 + m*64 + c4*4);
        }
        __syncthreads();

        // ---- GEMM1: qkv_head[64][96] = sx[64][192] @ sw[96][192]^T ----
        // warp tile: m16 x n48 (6 atoms), mw = warp&3, nw = warp>>2
        {
            const int m0 = (warp & 3) * 16;
            const int n0 = (warp >> 2) * 48;
            float acc[6][4];
            #pragma unroll
            for (int j = 0; j < 6; ++j)
                #pragma unroll
                for (int i = 0; i < 4; ++i) acc[j][i] = 0.f;

            const float* a0p = sx + (m0 + ln4)*XS + lc;
            const float* a1p = a0p + 8*XS;
            const float* bp[6];
            #pragma unroll
            for (int j = 0; j < 6; ++j) bp[j] = sw + (n0 + 8*j + ln4)*XS + lc;

            #pragma unroll 4
            for (int k0 = 0; k0 < CH; k0 += 8) {
                unsigned a[4];
                a[0] = ldb(a0p + k0);     a[1] = ldb(a1p + k0);
                a[2] = ldb(a0p + k0 + 4); a[3] = ldb(a1p + k0 + 4);
                #pragma unroll
                for (int j = 0; j < 6; ++j)
                    mma8(acc[j], a, ldb(bp[j] + k0), ldb(bp[j] + k0 + 4));
            }

            const int r0 = m0 + ln4;
            #pragma unroll
            for (int j = 0; j < 6; ++j) {
                const int nlo = n0 + 8*j;           // warp-uniform region selector
                const int n   = nlo + 2*lc;
                const float b0 = sb[n], b1 = sb[n+1];
                const float v00 = acc[j][0] + b0, v01 = acc[j][1] + b1;
                const float v10 = acc[j][2] + b0, v11 = acc[j][3] + b1;
                if (nlo < 32) {                     // q (pre-scaled)
                    sq[r0*QSQ + n]       = tfbits(v00 * scale);
                    sq[r0*QSQ + n+1]     = tfbits(v01 * scale);
                    sq[(r0+8)*QSQ + n]   = tfbits(v10 * scale);
                    sq[(r0+8)*QSQ + n+1] = tfbits(v11 * scale);
                } else if (nlo < 64) {              // k transposed [d][t]
                    skt[(n-32)*KS + r0]     = tfbits(v00);
                    skt[(n-31)*KS + r0]     = tfbits(v01);
                    skt[(n-32)*KS + r0+8]   = tfbits(v10);
                    skt[(n-31)*KS + r0+8]   = tfbits(v11);
                } else {                            // v
                    sv[r0*VS + (n-64)]      = tfbits(v00);
                    sv[r0*VS + (n-63)]      = tfbits(v01);
                    sv[(r0+8)*VS + (n-64)]  = tfbits(v10);
                    sv[(r0+8)*VS + (n-63)]  = tfbits(v11);
                }
            }
        }
        __syncthreads();

        // ---- GEMM2: scores[64][64] = q @ k^T  (+= staged bias in sp) ----
        // warp tile: m16 x n32 (4 atoms)
        {
            const int m0 = (warp & 3) * 16;
            const int n0 = (warp >> 2) * 32;
            float acc[4][4];
            #pragma unroll
            for (int j = 0; j < 4; ++j)
                #pragma unroll
                for (int i = 0; i < 4; ++i) acc[j][i] = 0.f;

            const float* a0p = sq + (m0 + ln4)*QSQ + lc;
            const float* a1p = a0p + 8*QSQ;
            const float* bp[4];
            #pragma unroll
            for (int j = 0; j < 4; ++j) bp[j] = skt + lc*KS + n0 + 8*j + ln4;

            #pragma unroll
            for (int k0 = 0; k0 < HDIM; k0 += 8) {
                unsigned a[4];
                a[0] = ldb(a0p + k0);     a[1] = ldb(a1p + k0);
                a[2] = ldb(a0p + k0 + 4); a[3] = ldb(a1p + k0 + 4);
                #pragma unroll
                for (int j = 0; j < 4; ++j)
                    mma8(acc[j], a, ldb(bp[j] + k0*KS), ldb(bp[j] + (k0+4)*KS));
            }

            const int r0 = m0 + ln4;
            #pragma unroll
            for (int j = 0; j < 4; ++j) {
                const int n = n0 + 8*j + 2*lc;
                sp[r0*PS + n]       += acc[j][0];
                sp[r0*PS + n+1]     += acc[j][1];
                sp[(r0+8)*PS + n]   += acc[j][2];
                sp[(r0+8)*PS + n+1] += acc[j][3];
            }
        }
        __syncthreads();

        // ---- softmax over rows of sp (4 lanes per row), write probs as tf32 ----
        {
            const int r    = tid >> 2;
            const int part = tid & 3;
            float* row = sp + r*PS + part*16;
            float mx = -1e30f;
            #pragma unroll
            for (int j = 0; j < 16; ++j) mx = fmaxf(mx, row[j]);
            mx = fmaxf(mx, __shfl_xor_sync(0xffffffffu, mx, 1));
            mx = fmaxf(mx, __shfl_xor_sync(0xffffffffu, mx, 2));
            float s = 0.f;
            float e[16];
            #pragma unroll
            for (int j = 0; j < 16; ++j) { e[j] = __expf(row[j] - mx); s += e[j]; }
            s += __shfl_xor_sync(0xffffffffu, s, 1);
            s += __shfl_xor_sync(0xffffffffu, s, 2);
            const float inv = 1.0f / s;
            #pragma unroll
            for (int j = 0; j < 16; ++j) row[j] = tfbits(e[j] * inv);
        }
        __syncthreads();

        // ---- GEMM3: out_h[64][32] = P[64][64] @ v[64][32] ----
        // warp tile: m16 x n16 (2 atoms)
        {
            const int m0 = (warp & 3) * 16;
            const int n0 = (warp >> 2) * 16;
            float acc[2][4];
            #pragma unroll
            for (int j = 0; j < 2; ++j)
                #pragma unroll
                for (int i = 0; i < 4; ++i) acc[j][i] = 0.f;

            const float* a0p = sp + (m0 + ln4)*PS + lc;
            const float* a1p = a0p + 8*PS;
            const float* bp[2];
            #pragma unroll
            for (int j = 0; j < 2; ++j) bp[j] = sv + lc*VS + n0 + 8*j + ln4;

            #pragma unroll
            for (int k0 = 0; k0 < 64; k0 += 8) {
                unsigned a[4];
                a[0] = ldb(a0p + k0);     a[1] = ldb(a1p + k0);
                a[2] = ldb(a0p + k0 + 4); a[3] = ldb(a1p + k0 + 4);
                #pragma unroll
                for (int j = 0; j < 2; ++j)
                    mma8(acc[j], a, ldb(bp[j] + k0*VS), ldb(bp[j] + (k0+4)*VS));
            }

            const int r0 = m0 + ln4;
            float* o = sout + h*HDIM;
            #pragma unroll
            for (int j = 0; j < 2; ++j) {
                const int n = n0 + 8*j + 2*lc;
                o[r0*XS + n]       = tfbits(acc[j][0]);
                o[r0*XS + n+1]     = tfbits(acc[j][1]);
                o[(r0+8)*XS + n]   = tfbits(acc[j][2]);
                o[(r0+8)*XS + n+1] = tfbits(acc[j][3]);
            }
        }
        __syncthreads();
    }

    // ---- projection: out[64][192] = sout @ proj_w^T + proj_b, 2 chunks of 96 cols ----
    for (int chunk = 0; chunk < 2; ++chunk) {
        for (int i = tid; i < 96*48; i += 256) {
            const int r  = i / 48;
            const int c4 = i % 48;
            float4 v = *(const float4*)(proj_w + (chunk*96 + r)*CH + c4*4);
            float* d = sw + r*XS + c4*4;
            d[0] = tfbits(v.x); d[1] = tfbits(v.y); d[2] = tfbits(v.z); d[3] = tfbits(v.w);
        }
        if (tid < 96) sb[tid] = proj_b[chunk*96 + tid];
        __syncthreads();

        {
            const int m0 = (warp & 3) * 16;
            const int n0 = (warp >> 2) * 48;
            float acc[6][4];
            #pragma unroll
            for (int j = 0; j < 6; ++j)
                #pragma unroll
                for (int i = 0; i < 4; ++i) acc[j][i] = 0.f;

            const float* a0p = sout + (m0 + ln4)*XS + lc;
            const float* a1p = a0p + 8*XS;
            const float* bp[6];
            #pragma unroll
            for (int j = 0; j < 6; ++j) bp[j] = sw + (n0 + 8*j + ln4)*XS + lc;

            #pragma unroll 4
            for (int k0 = 0; k0 < CH; k0 += 8) {
                unsigned a[4];
                a[0] = ldb(a0p + k0);     a[1] = ldb(a1p + k0);
                a[2] = ldb(a0p + k0 + 4); a[3] = ldb(a1p + k0 + 4);
                #pragma unroll
                for (int j = 0; j < 6; ++j)
                    mma8(acc[j], a, ldb(bp[j] + k0), ldb(bp[j] + k0 + 4));
            }

            const int r0 = m0 + ln4;
            #pragma unroll
            for (int j = 0; j < 6; ++j) {
                const int n = n0 + 8*j + 2*lc;
                const float b0 = sb[n], b1 = sb[n+1];
                pout[r0*OS + n]       = acc[j][0] + b0;
                pout[r0*OS + n+1]     = acc[j][1] + b1;
                pout[(r0+8)*OS + n]   = acc[j][2] + b0;
                pout[(r0+8)*OS + n+1] = acc[j][3] + b1;
            }
        }
        __syncthreads();

        // coalesced scatter back to global (24 float4 per token per chunk)
        for (int i = tid; i < 64*24; i += 256) {
            const int t  = i / 24;
            const int c4 = i % 24;
            const long long g = base + (long long)(t >> 3) * (IMGW*CH) + (t & 7) * CH
                              + chunk*96 + c4*4;
            *(float4*)(out + g) = *(const float4*)(pout + t*OS + c4*4);
        }
        __syncthreads();
    }
}

extern "C" void kernel_launch(void* const* d_in, const int* in_sizes, int n_in,
                              void* d_out, int out_size)
{
    const float* x      = (const float*)d_in[0];
    const float* qkv_w  = (const float*)d_in[1];
    const float* qkv_b  = (const float*)d_in[2];
    const float* proj_w = (const float*)d_in[3];
    const float* proj_b = (const float*)d_in[4];
    const float* bias   = (const float*)d_in[5];
    float* out = (float*)d_out;

    cudaFuncSetAttribute(win_attn_kernel,
                         cudaFuncAttributeMaxDynamicSharedMemorySize, SMEM_BYTES);

    const int n_windows = BATCH * (IMGH/8) * (IMGW/8);   // 4096
    win_attn_kernel<<<n_windows, 256, SMEM_BYTES>>>(x, qkv_w, qkv_b, proj_w, proj_b, bias, out);
}

// round 13
// speedup vs baseline: 1.4983x; 1.0994x over previous
#include <cuda_runtime.h>

// Swin-style window attention, fully fused per 8x8 window — tf32 tensor cores.
// B=4, H=W=256, C=192, NH=6, hd=32, WS=8 -> 4096 windows, 64 tokens each.
// One CTA of 512 threads (16 warps) per window. All GEMMs via mma.sync m16n8k8
// tf32, fp32 accumulate; softmax exact fp32. Weight staging for head h+1 is
// software-pipelined into head h's softmax section (sw only read by GEMM1).

#define BATCH 4
#define IMGH  256
#define IMGW  256
#define CH    192
#define NHEAD 6
#define HDIM  32

#define XS  196   // stride of 64x192 tiles (sx, sout) and 96x192 weight tile
#define QSQ 36    // sq stride      (A-loads: bank 4*ln4+lc, conflict-free)
#define KS  72    // skt stride     (B-loads: bank 8*lc+ln4, conflict-free)
#define VS  40    // sv stride      (B-loads: bank 8*lc+ln4, conflict-free)
#define PS  68    // sp stride      (A-loads: bank 4*ln4+lc, conflict-free)
#define OS  100   // proj staging stride

#define SMEM_FLOATS (64*XS + 64*XS + 96*XS + 64*QSQ + 32*KS + 64*VS + 64*PS + 96)
#define SMEM_BYTES  (SMEM_FLOATS * 4)

__device__ __forceinline__ unsigned f2tf(float f) {
    unsigned u;
    asm("cvt.rna.tf32.f32 %0, %1;" : "=r"(u) : "f"(f));
    return u;
}
__device__ __forceinline__ float tfbits(float f) {
    return __uint_as_float(f2tf(f));
}
__device__ __forceinline__ unsigned ldb(const float* p) {
    return __float_as_uint(*p);
}
__device__ __forceinline__ void mma8(float* d, const unsigned* a, unsigned b0, unsigned b1) {
    asm volatile(
        "mma.sync.aligned.m16n8k8.row.col.f32.tf32.tf32.f32 "
        "{%0,%1,%2,%3}, {%4,%5,%6,%7}, {%8,%9}, {%0,%1,%2,%3};"
        : "+f"(d[0]), "+f"(d[1]), "+f"(d[2]), "+f"(d[3])
        : "r"(a[0]), "r"(a[1]), "r"(a[2]), "r"(a[3]), "r"(b0), "r"(b1));
}

// stage 96 rows x 192 cols of a weight matrix into sw (tf32), rows via map
__device__ __forceinline__ void stage_qkv_w(float* sw, float* sb,
                                            const float* __restrict__ qkv_w,
                                            const float* __restrict__ qkv_b,
                                            int h, int tid)
{
    for (int i = tid; i < 96*48; i += 512) {
        const int r  = i / 48;
        const int c4 = i % 48;
        const int src = (r < 32) ? (h*HDIM + r)
                      : (r < 64) ? (CH + h*HDIM + (r - 32))
                                 : (2*CH + h*HDIM + (r - 64));
        float4 v = *(const float4*)(qkv_w + src*CH + c4*4);
        float* d = sw + r*XS + c4*4;
        d[0] = tfbits(v.x); d[1] = tfbits(v.y); d[2] = tfbits(v.z); d[3] = tfbits(v.w);
    }
    if (tid < 96) {
        const int r = tid;
        const int src = (r < 32) ? (h*HDIM + r)
                      : (r < 64) ? (CH + h*HDIM + (r - 32))
                                 : (2*CH + h*HDIM + (r - 64));
        sb[r] = qkv_b[src];
    }
}

__device__ __forceinline__ void stage_proj_w(float* sw, float* sb,
                                             const float* __restrict__ proj_w,
                                             const float* __restrict__ proj_b,
                                             int chunk, int tid)
{
    for (int i = tid; i < 96*48; i += 512) {
        const int r  = i / 48;
        const int c4 = i % 48;
        float4 v = *(const float4*)(proj_w + (chunk*96 + r)*CH + c4*4);
        float* d = sw + r*XS + c4*4;
        d[0] = tfbits(v.x); d[1] = tfbits(v.y); d[2] = tfbits(v.z); d[3] = tfbits(v.w);
    }
    if (tid < 96) sb[tid] = proj_b[chunk*96 + tid];
}

__global__ __launch_bounds__(512, 1)
void win_attn_kernel(const float* __restrict__ x,
                     const float* __restrict__ qkv_w,   // [576,192]
                     const float* __restrict__ qkv_b,   // [576]
                     const float* __restrict__ proj_w,  // [192,192]
                     const float* __restrict__ proj_b,  // [192]
                     const float* __restrict__ bias,    // [6,64,64]
                     float* __restrict__ out)
{
    extern __shared__ float sm[];
    float* sx   = sm;                // 64 x XS  : input window tile (tf32)
    float* sout = sx   + 64*XS;      // 64 x XS  : attention output accumulator (tf32)
    float* sw   = sout + 64*XS;      // 96 x XS  : weight staging (tf32)
    float* sq   = sw   + 96*XS;      // 64 x QSQ : q, pre-scaled (tf32)
    float* skt  = sq   + 64*QSQ;     // 32 x KS  : k transposed [d][t] (tf32)
    float* sv   = skt  + 32*KS;      // 64 x VS  : v (tf32)
    float* sp   = sv   + 64*VS;      // 64 x PS  : bias -> scores -> probs
    float* sb   = sp   + 64*PS;      // 96       : fp32 bias staging
    float* pout = sq;                // 64 x OS  : proj staging (fp32), reuses sq..sv

    const int tid  = threadIdx.x;
    const int warp = tid >> 5;
    const int lane = tid & 31;
    const int ln4  = lane >> 2;      // 0..7
    const int lc   = lane & 3;       // 0..3
    const int mw   = warp & 3;       // m-tile id (4)
    const int nw   = warp >> 2;      // n-tile id (4)
    const int m0   = mw * 16;

    const int w  = blockIdx.x;
    const int b  = w >> 10;
    const int wh = (w >> 5) & 31;
    const int ww = w & 31;
    const long long base = ((long long)b * (IMGH*IMGW) + (long long)(wh*8)*IMGW + (ww*8)) * CH;

    // ---- gather x window tile (tf32) + pre-stage head-0 weights ----
    for (int i = tid; i < 64*48; i += 512) {
        const int t  = i / 48;
        const int c4 = i % 48;
        const long long g = base + (long long)(t >> 3) * (IMGW*CH) + (t & 7) * CH + c4*4;
        float4 v = *(const float4*)(x + g);
        float* d = sx + t*XS + c4*4;
        d[0] = tfbits(v.x); d[1] = tfbits(v.y); d[2] = tfbits(v.z); d[3] = tfbits(v.w);
    }
    stage_qkv_w(sw, sb, qkv_w, qkv_b, 0, tid);
    __syncthreads();

    const float scale = 0.17677669529663687f; // 1/sqrt(32)

    for (int h = 0; h < NHEAD; ++h) {
        // ===== section A: stage attn-bias(h) into sp  +  GEMM1(h) =====
        for (int i = tid; i < 64*16; i += 512) {
            const int m  = i >> 4;
            const int c4 = i & 15;
            *(float4*)(sp + m*PS + c4*4) = *(const float4*)(bias + h*4096 + m*64 + c4*4);
        }
        // GEMM1: qkv_head[64][96] = sx[64][192] @ sw[96][192]^T, warp tile m16 x n24
        {
            const int n0 = nw * 24;
            float acc[3][4];
            #pragma unroll
            for (int j = 0; j < 3; ++j)
                #pragma unroll
                for (int i = 0; i < 4; ++i) acc[j][i] = 0.f;

            const float* a0p = sx + (m0 + ln4)*XS + lc;
            const float* a1p = a0p + 8*XS;
            const float* bp[3];
            #pragma unroll
            for (int j = 0; j < 3; ++j) bp[j] = sw + (n0 + 8*j + ln4)*XS + lc;

            #pragma unroll 4
            for (int k0 = 0; k0 < CH; k0 += 8) {
                unsigned a[4];
                a[0] = ldb(a0p + k0);     a[1] = ldb(a1p + k0);
                a[2] = ldb(a0p + k0 + 4); a[3] = ldb(a1p + k0 + 4);
                #pragma unroll
                for (int j = 0; j < 3; ++j)
                    mma8(acc[j], a, ldb(bp[j] + k0), ldb(bp[j] + k0 + 4));
            }

            const int r0 = m0 + ln4;
            #pragma unroll
            for (int j = 0; j < 3; ++j) {
                const int nlo = n0 + 8*j;             // warp-uniform region selector
                const int n   = nlo + 2*lc;
                const float b0 = sb[n], b1 = sb[n+1];
                const float v00 = acc[j][0] + b0, v01 = acc[j][1] + b1;
                const float v10 = acc[j][2] + b0, v11 = acc[j][3] + b1;
                if (nlo < 32) {                       // q (pre-scaled)
                    sq[r0*QSQ + n]       = tfbits(v00 * scale);
                    sq[r0*QSQ + n+1]     = tfbits(v01 * scale);
                    sq[(r0+8)*QSQ + n]   = tfbits(v10 * scale);
                    sq[(r0+8)*QSQ + n+1] = tfbits(v11 * scale);
                } else if (nlo < 64) {                // k transposed [d][t]
                    skt[(n-32)*KS + r0]     = tfbits(v00);
                    skt[(n-31)*KS + r0]     = tfbits(v01);
                    skt[(n-32)*KS + r0+8]   = tfbits(v10);
                    skt[(n-31)*KS + r0+8]   = tfbits(v11);
                } else {                              // v
                    sv[r0*VS + (n-64)]      = tfbits(v00);
                    sv[r0*VS + (n-63)]      = tfbits(v01);
                    sv[(r0+8)*VS + (n-64)]  = tfbits(v10);
                    sv[(r0+8)*VS + (n-63)]  = tfbits(v11);
                }
            }
        }
        __syncthreads();

        // ===== section B: GEMM2 scores[64][64] = q @ k^T (+= staged bias) =====
        {
            const int n0 = nw * 16;
            float acc[2][4];
            #pragma unroll
            for (int j = 0; j < 2; ++j)
                #pragma unroll
                for (int i = 0; i < 4; ++i) acc[j][i] = 0.f;

            const float* a0p = sq + (m0 + ln4)*QSQ + lc;
            const float* a1p = a0p + 8*QSQ;
            const float* bp[2];
            #pragma unroll
            for (int j = 0; j < 2; ++j) bp[j] = skt + lc*KS + n0 + 8*j + ln4;

            #pragma unroll
            for (int k0 = 0; k0 < HDIM; k0 += 8) {
                unsigned a[4];
                a[0] = ldb(a0p + k0);     a[1] = ldb(a1p + k0);
                a[2] = ldb(a0p + k0 + 4); a[3] = ldb(a1p + k0 + 4);
                #pragma unroll
                for (int j = 0; j < 2; ++j)
                    mma8(acc[j], a, ldb(bp[j] + k0*KS), ldb(bp[j] + (k0+4)*KS));
            }

            const int r0 = m0 + ln4;
            #pragma unroll
            for (int j = 0; j < 2; ++j) {
                const int n = n0 + 8*j + 2*lc;
                sp[r0*PS + n]       += acc[j][0];
                sp[r0*PS + n+1]     += acc[j][1];
                sp[(r0+8)*PS + n]   += acc[j][2];
                sp[(r0+8)*PS + n+1] += acc[j][3];
            }
        }
        __syncthreads();

        // ===== section C: prefetch next weights (sw free)  +  softmax =====
        if (h < NHEAD-1) stage_qkv_w(sw, sb, qkv_w, qkv_b, h+1, tid);
        else             stage_proj_w(sw, sb, proj_w, proj_b, 0, tid);
        {
            const int r    = tid >> 3;       // 0..63
            const int part = tid & 7;        // 0..7, 8 cols each
            float* row = sp + r*PS + part*8;
            float4 v0 = *(float4*)row;
            float4 v1 = *(float4*)(row + 4);
            float mx = fmaxf(fmaxf(fmaxf(v0.x, v0.y), fmaxf(v0.z, v0.w)),
                             fmaxf(fmaxf(v1.x, v1.y), fmaxf(v1.z, v1.w)));
            mx = fmaxf(mx, __shfl_xor_sync(0xffffffffu, mx, 1));
            mx = fmaxf(mx, __shfl_xor_sync(0xffffffffu, mx, 2));
            mx = fmaxf(mx, __shfl_xor_sync(0xffffffffu, mx, 4));
            float e[8];
            e[0]=__expf(v0.x-mx); e[1]=__expf(v0.y-mx); e[2]=__expf(v0.z-mx); e[3]=__expf(v0.w-mx);
            e[4]=__expf(v1.x-mx); e[5]=__expf(v1.y-mx); e[6]=__expf(v1.z-mx); e[7]=__expf(v1.w-mx);
            float s = ((e[0]+e[1])+(e[2]+e[3])) + ((e[4]+e[5])+(e[6]+e[7]));
            s += __shfl_xor_sync(0xffffffffu, s, 1);
            s += __shfl_xor_sync(0xffffffffu, s, 2);
            s += __shfl_xor_sync(0xffffffffu, s, 4);
            const float inv = 1.0f / s;
            float4 o0, o1;
            o0.x=tfbits(e[0]*inv); o0.y=tfbits(e[1]*inv); o0.z=tfbits(e[2]*inv); o0.w=tfbits(e[3]*inv);
            o1.x=tfbits(e[4]*inv); o1.y=tfbits(e[5]*inv); o1.z=tfbits(e[6]*inv); o1.w=tfbits(e[7]*inv);
            *(float4*)row       = o0;
            *(float4*)(row + 4) = o1;
        }
        __syncthreads();

        // ===== section D: GEMM3 out_h[64][32] = P[64][64] @ v[64][32] =====
        {
            const int n0 = nw * 8;
            float acc[4] = {0.f, 0.f, 0.f, 0.f};

            const float* a0p = sp + (m0 + ln4)*PS + lc;
            const float* a1p = a0p + 8*PS;
            const float* bp  = sv + lc*VS + n0 + ln4;

            #pragma unroll
            for (int k0 = 0; k0 < 64; k0 += 8) {
                unsigned a[4];
                a[0] = ldb(a0p + k0);     a[1] = ldb(a1p + k0);
                a[2] = ldb(a0p + k0 + 4); a[3] = ldb(a1p + k0 + 4);
                mma8(acc, a, ldb(bp + k0*VS), ldb(bp + (k0+4)*VS));
            }

            const int r0 = m0 + ln4;
            float* o = sout + h*HDIM;
            const int n = n0 + 2*lc;
            o[r0*XS + n]       = tfbits(acc[0]);
            o[r0*XS + n+1]     = tfbits(acc[1]);
            o[(r0+8)*XS + n]   = tfbits(acc[2]);
            o[(r0+8)*XS + n+1] = tfbits(acc[3]);
        }
        __syncthreads();
    }

    // ---- projection: out[64][192] = sout @ proj_w^T + proj_b, 2 chunks of 96 ----
    for (int chunk = 0; chunk < 2; ++chunk) {
        // chunk-0 weights were staged during head 5's softmax; chunk-1 during
        // chunk-0's scatter.
        {
            const int n0 = nw * 24;
            float acc[3][4];
            #pragma unroll
            for (int j = 0; j < 3; ++j)
                #pragma unroll
                for (int i = 0; i < 4; ++i) acc[j][i] = 0.f;

            const float* a0p = sout + (m0 + ln4)*XS + lc;
            const float* a1p = a0p + 8*XS;
            const float* bp[3];
            #pragma unroll
            for (int j = 0; j < 3; ++j) bp[j] = sw + (n0 + 8*j + ln4)*XS + lc;

            #pragma unroll 4
            for (int k0 = 0; k0 < CH; k0 += 8) {
                unsigned a[4];
                a[0] = ldb(a0p + k0);     a[1] = ldb(a1p + k0);
                a[2] = ldb(a0p + k0 + 4); a[3] = ldb(a1p + k0 + 4);
                #pragma unroll
                for (int j = 0; j < 3; ++j)
                    mma8(acc[j], a, ldb(bp[j] + k0), ldb(bp[j] + k0 + 4));
            }

            const int r0 = m0 + ln4;
            #pragma unroll
            for (int j = 0; j < 3; ++j) {
                const int n = n0 + 8*j + 2*lc;
                const float b0 = sb[n], b1 = sb[n+1];
                pout[r0*OS + n]       = acc[j][0] + b0;
                pout[r0*OS + n+1]     = acc[j][1] + b1;
                pout[(r0+8)*OS + n]   = acc[j][2] + b0;
                pout[(r0+8)*OS + n+1] = acc[j][3] + b1;
            }
        }
        __syncthreads();

        // coalesced scatter back to global + prefetch chunk-1 weights
        for (int i = tid; i < 64*24; i += 512) {
            const int t  = i / 24;
            const int c4 = i % 24;
            const long long g = base + (long long)(t >> 3) * (IMGW*CH) + (t & 7) * CH
                              + chunk*96 + c4*4;
            *(float4*)(out + g) = *(const float4*)(pout + t*OS + c4*4);
        }
        if (chunk == 0) {
            stage_proj_w(sw, sb, proj_w, proj_b, 1, tid);
            __syncthreads();
        }
    }
}

extern "C" void kernel_launch(void* const* d_in, const int* in_sizes, int n_in,
                              void* d_out, int out_size)
{
    const float* x      = (const float*)d_in[0];
    const float* qkv_w  = (const float*)d_in[1];
    const float* qkv_b  = (const float*)d_in[2];
    const float* proj_w = (const float*)d_in[3];
    const float* proj_b = (const float*)d_in[4];
    const float* bias   = (const float*)d_in[5];
    float* out = (float*)d_out;

    cudaFuncSetAttribute(win_attn_kernel,
                         cudaFuncAttributeMaxDynamicSharedMemorySize, SMEM_BYTES);

    const int n_windows = BATCH * (IMGH/8) * (IMGW/8);   // 4096
    win_attn_kernel<<<n_windows, 512, SMEM_BYTES>>>(x, qkv_w, qkv_b, proj_w, proj_b, bias, out);
}

// round 15
// speedup vs baseline: 2.4815x; 1.6562x over previous
#include <cuda_runtime.h>
#include <cuda_fp16.h>

// Swin window attention, fused per 8x8 window — fp16 tensor cores (m16n8k16),
// fp32 accumulate, register-resident softmax (no smem for scores/probs).
// B=4, 256x256, C=192, NH=6, hd=32 -> 4096 windows. 512 threads / 16 warps.
//
// Phases: (1) QKV for all 6 heads into fp16 smem (double-buffered weight
// staging, 6 chunks), (2) barrier-free attention: warp-local tasks
// (head, 16-row strip), (3) projection, direct STG to global.

#define BATCH 4
#define IMGH  256
#define IMGW  256
#define CH    192
#define NHEAD 6
#define HDIM  32

// strides in halfs
#define SXS 200   // sx / sout / sw rows
#define QKS 40    // sq / sk rows
#define VTS 72    // svt rows

// smem byte offsets
#define SX_OFF   0                       // 64*200*2   = 25600  (sx, later sout)
#define SW_OFF   25600                   // 2 * 96*200*2 = 76800 (double buffer)
#define SWHALF   19200                   // halfs per sw buffer
#define SQ_OFF   102400                  // 6*64*40*2  = 30720
#define SK_OFF   133120                  // 6*64*40*2  = 30720
#define SVT_OFF  163840                  // 6*32*72*2  = 27648
#define SBQ_OFF  191488                  // 576*4      = 2304
#define SBP_OFF  193792                  // 192*4      = 768
#define SMEM_BYTES 194560

__device__ __forceinline__ unsigned pk(float lo, float hi) {
    __half2 h = __floats2half2_rn(lo, hi);
    return *reinterpret_cast<unsigned*>(&h);
}
__device__ __forceinline__ unsigned ldu(const __half* p) {
    return *reinterpret_cast<const unsigned*>(p);
}
__device__ __forceinline__ void mma16(float* d, const unsigned* a, unsigned b0, unsigned b1) {
    asm volatile(
        "mma.sync.aligned.m16n8k16.row.col.f32.f16.f16.f32 "
        "{%0,%1,%2,%3}, {%4,%5,%6,%7}, {%8,%9}, {%0,%1,%2,%3};"
        : "+f"(d[0]), "+f"(d[1]), "+f"(d[2]), "+f"(d[3])
        : "r"(a[0]), "r"(a[1]), "r"(a[2]), "r"(a[3]), "r"(b0), "r"(b1));
}

// stage 96 rows x 192 cols of qkv_w (head chunk c) into dst as fp16
__device__ __forceinline__ void stage_qkv(__half* dst, const float* __restrict__ qkv_w,
                                          int c, int idx0, int step)
{
    for (int i = idx0; i < 96*48; i += step) {
        const int r  = i / 48;
        const int c4 = i % 48;
        const int gr = (r < 32) ? (c*32 + r)
                     : (r < 64) ? (CH + c*32 + (r - 32))
                                : (2*CH + c*32 + (r - 64));
        float4 v = *(const float4*)(qkv_w + gr*CH + c4*4);
        *(uint2*)(dst + r*SXS + c4*4) = make_uint2(pk(v.x, v.y), pk(v.z, v.w));
    }
}

__device__ __forceinline__ void stage_proj(__half* dst, const float* __restrict__ proj_w,
                                           int chunk, int idx0, int step)
{
    for (int i = idx0; i < 96*48; i += step) {
        const int r  = i / 48;
        const int c4 = i % 48;
        float4 v = *(const float4*)(proj_w + (chunk*96 + r)*CH + c4*4);
        *(uint2*)(dst + r*SXS + c4*4) = make_uint2(pk(v.x, v.y), pk(v.z, v.w));
    }
}

__global__ __launch_bounds__(512, 1)
void win_attn_kernel(const float* __restrict__ x,
                     const float* __restrict__ qkv_w,   // [576,192]
                     const float* __restrict__ qkv_b,   // [576]
                     const float* __restrict__ proj_w,  // [192,192]
                     const float* __restrict__ proj_b,  // [192]
                     const float* __restrict__ bias,    // [6,64,64]
                     float* __restrict__ out)
{
    extern __shared__ char smem[];
    __half* sx   = (__half*)(smem + SX_OFF);    // 64 x SXS, aliased as sout later
    __half* swb  = (__half*)(smem + SW_OFF);    // 2 x (96 x SXS)
    __half* sq   = (__half*)(smem + SQ_OFF);    // [6][64][QKS] q (pre-scaled)
    __half* sk   = (__half*)(smem + SK_OFF);    // [6][64][QKS] k  ([token][d])
    __half* svt  = (__half*)(smem + SVT_OFF);   // [6][32][VTS] v transposed [d][token]
    float*  sbq  = (float*)(smem + SBQ_OFF);    // qkv_b[576]
    float*  sbp  = (float*)(smem + SBP_OFF);    // proj_b[192]

    const int tid  = threadIdx.x;
    const int warp = tid >> 5;
    const int lane = tid & 31;
    const int g    = lane >> 2;   // 0..7
    const int lc   = lane & 3;    // 0..3

    const int w  = blockIdx.x;
    const int b  = w >> 10;
    const int wh = (w >> 5) & 31;
    const int ww = w & 31;
    const long long base = ((long long)b * (IMGH*IMGW) + (long long)(wh*8)*IMGW + (ww*8)) * CH;

    // ---- gather x -> fp16 sx; stage chunk0 weights; stage biases ----
    for (int i = tid; i < 64*48; i += 512) {
        const int t  = i / 48;
        const int c4 = i % 48;
        const long long ga = base + (long long)(t >> 3) * (IMGW*CH) + (t & 7) * CH + c4*4;
        float4 v = *(const float4*)(x + ga);
        *(uint2*)(sx + t*SXS + c4*4) = make_uint2(pk(v.x, v.y), pk(v.z, v.w));
    }
    stage_qkv(swb, qkv_w, 0, tid, 512);
    for (int i = tid; i < 576; i += 512) sbq[i] = qkv_b[i];
    if (tid < 192) sbp[tid] = proj_b[tid];
    __syncthreads();

    const float scale = 0.17677669529663687f; // 1/sqrt(32)
    const int mw = warp & 3;
    const int nw = warp >> 2;

    // ================= phase 1: QKV for all heads =================
    for (int c = 0; c < NHEAD; ++c) {
        const __half* swc = swb + (c & 1) * SWHALF;
        const int m0 = mw * 16;
        const int n0 = nw * 24;
        float acc[3][4];
        #pragma unroll
        for (int j = 0; j < 3; ++j)
            #pragma unroll
            for (int i = 0; i < 4; ++i) acc[j][i] = 0.f;

        const __half* a0 = sx + (m0 + g)*SXS + 2*lc;
        const __half* b0p[3];
        #pragma unroll
        for (int j = 0; j < 3; ++j) b0p[j] = swc + (n0 + 8*j + g)*SXS + 2*lc;

        #pragma unroll 4
        for (int k0 = 0; k0 < CH; k0 += 16) {
            unsigned a[4];
            a[0] = ldu(a0 + k0);           a[1] = ldu(a0 + 8*SXS + k0);
            a[2] = ldu(a0 + k0 + 8);       a[3] = ldu(a0 + 8*SXS + k0 + 8);
            #pragma unroll
            for (int j = 0; j < 3; ++j)
                mma16(acc[j], a, ldu(b0p[j] + k0), ldu(b0p[j] + k0 + 8));
        }

        // epilogue: bias + scatter into sq / sk / svt (head c)
        const int r0 = m0 + g;
        __half* sqh = sq  + c * 64*QKS;
        __half* skh = sk  + c * 64*QKS;
        __half* svh = svt + c * 32*VTS;
        #pragma unroll
        for (int j = 0; j < 3; ++j) {
            const int nlo = n0 + 8*j;               // warp-uniform
            const int n   = nlo + 2*lc;
            const int src = (n < 32) ? (c*32 + n)
                          : (n < 64) ? (CH + c*32 + (n - 32))
                                     : (2*CH + c*32 + (n - 64));
            const float bb0 = sbq[src], bb1 = sbq[src + 1];
            const float v00 = acc[j][0] + bb0, v01 = acc[j][1] + bb1;
            const float v10 = acc[j][2] + bb0, v11 = acc[j][3] + bb1;
            if (nlo < 32) {
                *(unsigned*)(sqh + r0*QKS + n)     = pk(v00*scale, v01*scale);
                *(unsigned*)(sqh + (r0+8)*QKS + n) = pk(v10*scale, v11*scale);
            } else if (nlo < 64) {
                *(unsigned*)(skh + r0*QKS + (n-32))     = pk(v00, v01);
                *(unsigned*)(skh + (r0+8)*QKS + (n-32)) = pk(v10, v11);
            } else {
                const int d0 = n - 64;
                svh[d0*VTS + r0]         = __float2half_rn(v00);
                svh[(d0+1)*VTS + r0]     = __float2half_rn(v01);
                svh[d0*VTS + r0 + 8]     = __float2half_rn(v10);
                svh[(d0+1)*VTS + r0 + 8] = __float2half_rn(v11);
            }
        }

        // stage next weights into the other buffer (proj chunk 0 after last head)
        if (c < NHEAD-1) stage_qkv(swb + ((c+1) & 1) * SWHALF, qkv_w, c+1, tid, 512);
        else             stage_proj(swb, proj_w, 0, tid, 512);
        __syncthreads();
    }

    // ================= phase 2: attention, warp-local tasks =================
    // 24 tasks = (head 0..5) x (16-row strip 0..3). Warps 0..15 take task=warp,
    // warps 0..7 also take task=16+warp; warps 8..15 stage proj chunk 1 instead.
    #pragma unroll 1
    for (int slot = 0; slot < 2; ++slot) {
        const int task = slot == 0 ? warp : 16 + warp;
        if (slot == 1 && warp >= 8) {
            stage_proj(swb + SWHALF, proj_w, 1, (warp - 8)*32 + lane, 256);
            continue;
        }
        const int h  = task >> 2;
        const int m0 = (task & 3) * 16;
        const __half* sqh = sq  + h * 64*QKS;
        const __half* skh = sk  + h * 64*QKS;
        const __half* svh = svt + h * 32*VTS;

        // scores m16 x n64, K=32 (2 k-steps)
        float acc[8][4];
        #pragma unroll
        for (int j = 0; j < 8; ++j)
            #pragma unroll
            for (int i = 0; i < 4; ++i) acc[j][i] = 0.f;

        const __half* aq = sqh + (m0 + g)*QKS + 2*lc;
        #pragma unroll
        for (int kk = 0; kk < 2; ++kk) {
            const int k0 = kk * 16;
            unsigned a[4];
            a[0] = ldu(aq + k0);           a[1] = ldu(aq + 8*QKS + k0);
            a[2] = ldu(aq + k0 + 8);       a[3] = ldu(aq + 8*QKS + k0 + 8);
            #pragma unroll
            for (int j = 0; j < 8; ++j) {
                const __half* bkp = skh + (8*j + g)*QKS + 2*lc + k0;
                mma16(acc[j], a, ldu(bkp), ldu(bkp + 8));
            }
        }

        // + bias (direct from global, L2-resident), then register softmax
        const float* bp = bias + h*4096 + (m0 + g)*64 + 2*lc;
        float mx0 = -1e30f, mx1 = -1e30f;
        #pragma unroll
        for (int j = 0; j < 8; ++j) {
            const float2 bA = *(const float2*)(bp + 8*j);
            const float2 bB = *(const float2*)(bp + 512 + 8*j);   // row + 8
            acc[j][0] += bA.x; acc[j][1] += bA.y;
            acc[j][2] += bB.x; acc[j][3] += bB.y;
            mx0 = fmaxf(mx0, fmaxf(acc[j][0], acc[j][1]));
            mx1 = fmaxf(mx1, fmaxf(acc[j][2], acc[j][3]));
        }
        mx0 = fmaxf(mx0, __shfl_xor_sync(0xffffffffu, mx0, 1));
        mx0 = fmaxf(mx0, __shfl_xor_sync(0xffffffffu, mx0, 2));
        mx1 = fmaxf(mx1, __shfl_xor_sync(0xffffffffu, mx1, 1));
        mx1 = fmaxf(mx1, __shfl_xor_sync(0xffffffffu, mx1, 2));
        float s0 = 0.f, s1 = 0.f;
        #pragma unroll
        for (int j = 0; j < 8; ++j) {
            acc[j][0] = __expf(acc[j][0] - mx0); acc[j][1] = __expf(acc[j][1] - mx0);
            acc[j][2] = __expf(acc[j][2] - mx1); acc[j][3] = __expf(acc[j][3] - mx1);
            s0 += acc[j][0] + acc[j][1];
            s1 += acc[j][2] + acc[j][3];
        }
        s0 += __shfl_xor_sync(0xffffffffu, s0, 1);
        s0 += __shfl_xor_sync(0xffffffffu, s0, 2);
        s1 += __shfl_xor_sync(0xffffffffu, s1, 1);
        s1 += __shfl_xor_sync(0xffffffffu, s1, 2);
        const float inv0 = 1.0f / s0, inv1 = 1.0f / s1;

        // pack probs: D-fragment layout == A-fragment layout for P@V
        unsigned pa[8], pb[8];
        #pragma unroll
        for (int j = 0; j < 8; ++j) {
            pa[j] = pk(acc[j][0]*inv0, acc[j][1]*inv0);
            pb[j] = pk(acc[j][2]*inv1, acc[j][3]*inv1);
        }

        // out_h m16 x n32, K=64 (4 k-steps); B from v-transposed [d][token]
        float oacc[4][4];
        #pragma unroll
        for (int j = 0; j < 4; ++j)
            #pragma unroll
            for (int i = 0; i < 4; ++i) oacc[j][i] = 0.f;
        #pragma unroll
        for (int kk = 0; kk < 4; ++kk) {
            unsigned a[4] = { pa[2*kk], pb[2*kk], pa[2*kk+1], pb[2*kk+1] };
            #pragma unroll
            for (int jj = 0; jj < 4; ++jj) {
                const __half* bvp = svh + (8*jj + g)*VTS + 2*lc + 16*kk;
                mma16(oacc[jj], a, ldu(bvp), ldu(bvp + 8));
            }
        }

        // write to sout (= sx region), cols h*32 + ...
        __half* so = sx + (m0 + g)*SXS + h*HDIM;
        #pragma unroll
        for (int jj = 0; jj < 4; ++jj) {
            const int cc = 8*jj + 2*lc;
            *(unsigned*)(so + cc)         = pk(oacc[jj][0], oacc[jj][1]);
            *(unsigned*)(so + 8*SXS + cc) = pk(oacc[jj][2], oacc[jj][3]);
        }
    }
    __syncthreads();

    // ================= phase 3: projection, direct global store =================
    #pragma unroll 1
    for (int chunk = 0; chunk < 2; ++chunk) {
        const __half* swc = swb + chunk * SWHALF;
        const int m0 = mw * 16;
        const int n0 = nw * 24;
        float acc[3][4];
        #pragma unroll
        for (int j = 0; j < 3; ++j)
            #pragma unroll
            for (int i = 0; i < 4; ++i) acc[j][i] = 0.f;

        const __half* a0 = sx + (m0 + g)*SXS + 2*lc;   // sout
        const __half* b0p[3];
        #pragma unroll
        for (int j = 0; j < 3; ++j) b0p[j] = swc + (n0 + 8*j + g)*SXS + 2*lc;

        #pragma unroll 4
        for (int k0 = 0; k0 < CH; k0 += 16) {
            unsigned a[4];
            a[0] = ldu(a0 + k0);           a[1] = ldu(a0 + 8*SXS + k0);
            a[2] = ldu(a0 + k0 + 8);       a[3] = ldu(a0 + 8*SXS + k0 + 8);
            #pragma unroll
            for (int j = 0; j < 3; ++j)
                mma16(acc[j], a, ldu(b0p[j] + k0), ldu(b0p[j] + k0 + 8));
        }

        const int t0 = m0 + g;
        const int t1 = t0 + 8;
        const long long ga0 = base + (long long)(t0 >> 3) * (IMGW*CH) + (t0 & 7) * CH;
        const long long ga1 = base + (long long)(t1 >> 3) * (IMGW*CH) + (t1 & 7) * CH;
        #pragma unroll
        for (int j = 0; j < 3; ++j) {
            const int n = chunk*96 + n0 + 8*j + 2*lc;
            const float bb0 = sbp[n], bb1 = sbp[n + 1];
            *(float2*)(out + ga0 + n) = make_float2(acc[j][0] + bb0, acc[j][1] + bb1);
            *(float2*)(out + ga1 + n) = make_float2(acc[j][2] + bb0, acc[j][3] + bb1);
        }
    }
}

extern "C" void kernel_launch(void* const* d_in, const int* in_sizes, int n_in,
                              void* d_out, int out_size)
{
    const float* x      = (const float*)d_in[0];
    const float* qkv_w  = (const float*)d_in[1];
    const float* qkv_b  = (const float*)d_in[2];
    const float* proj_w = (const float*)d_in[3];
    const float* proj_b = (const float*)d_in[4];
    const float* bias   = (const float*)d_in[5];
    float* out = (float*)d_out;

    cudaFuncSetAttribute(win_attn_kernel,
                         cudaFuncAttributeMaxDynamicSharedMemorySize, SMEM_BYTES);

    const int n_windows = BATCH * (IMGH/8) * (IMGW/8);   // 4096
    win_attn_kernel<<<n_windows, 512, SMEM_BYTES>>>(x, qkv_w, qkv_b, proj_w, proj_b, bias, out);
}

// round 16
// speedup vs baseline: 6.4290x; 2.5907x over previous
#include <cuda_runtime.h>
#include <cuda_fp16.h>

// Swin window attention, fused per 8x8 window — fp16 tensor cores (m16n8k16).
// R16: 2 CTAs/SM. Weights pre-packed to fragment-major fp16 in __device__
// globals by a prep kernel; B operands come straight from L2 (no smem weight
// staging). 384 threads / 12 warps; only 3 CTA-wide barriers.
// smem/CTA = 105 KB -> 2 CTAs resident; __launch_bounds__(384,2).

#define BATCH 4
#define IMGH  256
#define IMGW  256
#define CH    192
#define NHEAD 6
#define HDIM  32

#define SXS 200   // row stride (halfs) for sx/sout, sq, sk
#define VTS 72    // row stride (halfs) for v-transposed

// smem byte offsets
#define SX_OFF   0         // 64*200*2 = 25600 (x, later attention output)
#define SQ_OFF   25600     // 64*200*2 = 25600 (q all heads, col h*32)
#define SK_OFF   51200     // 64*200*2 = 25600 (k all heads, col h*32)
#define SVT_OFF  76800     // 192*72*2 = 27648 (v^T all heads, row h*32+d)
#define SBQ_OFF  104448    // 576*4
#define SBP_OFF  106752    // 192*4
#define SMEM_BYTES 107520

// fragment-major weights: frag id = ((chunk*12 + jglob)*12 + ks), 32 lanes each
#define QKV_FRAGS  (6*12*12*32)   // 27648
#define PROJ_FRAGS (2*12*12*32)   // 9216
__device__ uint2 d_qkv_wf[QKV_FRAGS];
__device__ uint2 d_proj_wf[PROJ_FRAGS];

__device__ __forceinline__ unsigned pk(float lo, float hi) {
    __half2 h = __floats2half2_rn(lo, hi);
    return *reinterpret_cast<unsigned*>(&h);
}
__device__ __forceinline__ unsigned ldu(const __half* p) {
    return *reinterpret_cast<const unsigned*>(p);
}
__device__ __forceinline__ void mma16(float* d, const unsigned* a, unsigned b0, unsigned b1) {
    asm volatile(
        "mma.sync.aligned.m16n8k16.row.col.f32.f16.f16.f32 "
        "{%0,%1,%2,%3}, {%4,%5,%6,%7}, {%8,%9}, {%0,%1,%2,%3};"
        : "+f"(d[0]), "+f"(d[1]), "+f"(d[2]), "+f"(d[3])
        : "r"(a[0]), "r"(a[1]), "r"(a[2]), "r"(a[3]), "r"(b0), "r"(b1));
}

// ---- prep: pack weights into fragment-major fp16 (one LDG.64 per lane) ----
__global__ void prep_weights(const float* __restrict__ qkv_w,
                             const float* __restrict__ proj_w)
{
    const int idx = blockIdx.x * 256 + threadIdx.x;
    if (idx < QKV_FRAGS) {
        const int lane = idx & 31;
        const int g  = lane >> 2, lc = lane & 3;
        int rest = idx >> 5;
        const int ks = rest % 12; rest /= 12;
        const int j  = rest % 12; rest /= 12;
        const int c  = rest;                   // head chunk 0..5
        const int n  = 8*j + g;                // 0..95 within chunk
        const int gr = (n < 32) ? (c*32 + n)
                     : (n < 64) ? (CH + c*32 + (n - 32))
                                : (2*CH + c*32 + (n - 64));
        const float* wr = qkv_w + gr*CH + ks*16 + 2*lc;
        d_qkv_wf[idx] = make_uint2(pk(wr[0], wr[1]), pk(wr[8], wr[9]));
    } else if (idx < QKV_FRAGS + PROJ_FRAGS) {
        const int p = idx - QKV_FRAGS;
        const int lane = p & 31;
        const int g  = lane >> 2, lc = lane & 3;
        int rest = p >> 5;
        const int ks = rest % 12; rest /= 12;
        const int j  = rest % 12; rest /= 12;
        const int chunk = rest;                // 0..1
        const int gr = chunk*96 + 8*j + g;
        const float* wr = proj_w + gr*CH + ks*16 + 2*lc;
        d_proj_wf[p] = make_uint2(pk(wr[0], wr[1]), pk(wr[8], wr[9]));
    }
}

__global__ __launch_bounds__(384, 2)
void win_attn_kernel(const float* __restrict__ x,
                     const float* __restrict__ qkv_b,   // [576]
                     const float* __restrict__ proj_b,  // [192]
                     const float* __restrict__ bias,    // [6,64,64]
                     float* __restrict__ out)
{
    extern __shared__ char smem[];
    __half* sx  = (__half*)(smem + SX_OFF);    // 64 x SXS (x, later sout)
    __half* sq  = (__half*)(smem + SQ_OFF);    // 64 x SXS, head h at col h*32
    __half* sk  = (__half*)(smem + SK_OFF);    // 64 x SXS, head h at col h*32
    __half* svt = (__half*)(smem + SVT_OFF);   // 192 x VTS, [h*32+d][token]
    float*  sbq = (float*)(smem + SBQ_OFF);
    float*  sbp = (float*)(smem + SBP_OFF);

    const int tid  = threadIdx.x;
    const int warp = tid >> 5;        // 0..11
    const int lane = tid & 31;
    const int g    = lane >> 2;       // 0..7
    const int lc   = lane & 3;        // 0..3
    const int mw   = warp & 3;        // m strip 0..3
    const int nwt  = warp >> 2;       // n group 0..2
    const int m0   = mw * 16;

    const int w  = blockIdx.x;
    const int b  = w >> 10;
    const int wh = (w >> 5) & 31;
    const int ww = w & 31;
    const long long base = ((long long)b * (IMGH*IMGW) + (long long)(wh*8)*IMGW + (ww*8)) * CH;

    // ---- gather x -> fp16 sx; biases -> smem ----
    for (int i = tid; i < 64*48; i += 384) {
        const int t  = i / 48;
        const int c4 = i % 48;
        const long long ga = base + (long long)(t >> 3) * (IMGW*CH) + (t & 7) * CH + c4*4;
        float4 v = *(const float4*)(x + ga);
        *(uint2*)(sx + t*SXS + c4*4) = make_uint2(pk(v.x, v.y), pk(v.z, v.w));
    }
    for (int i = tid; i < 576; i += 384) sbq[i] = qkv_b[i];
    if (tid < 192) sbp[tid] = proj_b[tid];
    __syncthreads();

    const float scale = 0.17677669529663687f; // 1/sqrt(32)

    // ================= phase 1: QKV, all heads, no internal barriers =========
    for (int c = 0; c < NHEAD; ++c) {
        // warp computes m16 x n32: n-tiles jglob = nwt*4 .. nwt*4+3
        const uint2* wfb = d_qkv_wf + ((c*12 + nwt*4)*12)*32 + lane;
        float acc[4][4];
        #pragma unroll
        for (int j = 0; j < 4; ++j)
            #pragma unroll
            for (int i = 0; i < 4; ++i) acc[j][i] = 0.f;

        const __half* a0 = sx + (m0 + g)*SXS + 2*lc;

        #pragma unroll 2
        for (int ks = 0; ks < 12; ++ks) {
            const int k0 = ks * 16;
            unsigned a[4];
            a[0] = ldu(a0 + k0);       a[1] = ldu(a0 + 8*SXS + k0);
            a[2] = ldu(a0 + k0 + 8);   a[3] = ldu(a0 + 8*SXS + k0 + 8);
            #pragma unroll
            for (int j = 0; j < 4; ++j) {
                const uint2 bb = __ldg(wfb + (j*12 + ks)*32);
                mma16(acc[j], a, bb.x, bb.y);
            }
        }

        // epilogue: warp-specialized scatter (nwt: 0->q, 1->k, 2->v)
        const int r0 = m0 + g;
        if (nwt == 0) {                       // q, pre-scaled, col c*32+n
            #pragma unroll
            for (int j = 0; j < 4; ++j) {
                const int n = 8*j + 2*lc;
                const float b0 = sbq[c*32 + n], b1 = sbq[c*32 + n + 1];
                *(unsigned*)(sq + r0*SXS + c*32 + n) =
                    pk((acc[j][0]+b0)*scale, (acc[j][1]+b1)*scale);
                *(unsigned*)(sq + (r0+8)*SXS + c*32 + n) =
                    pk((acc[j][2]+b0)*scale, (acc[j][3]+b1)*scale);
            }
        } else if (nwt == 1) {                // k
            #pragma unroll
            for (int j = 0; j < 4; ++j) {
                const int n = 8*j + 2*lc;
                const float b0 = sbq[CH + c*32 + n], b1 = sbq[CH + c*32 + n + 1];
                *(unsigned*)(sk + r0*SXS + c*32 + n) = pk(acc[j][0]+b0, acc[j][1]+b1);
                *(unsigned*)(sk + (r0+8)*SXS + c*32 + n) = pk(acc[j][2]+b0, acc[j][3]+b1);
            }
        } else {                              // v transposed [h*32+d][token]
            #pragma unroll
            for (int j = 0; j < 4; ++j) {
                const int d0 = 8*j + 2*lc;
                const float b0 = sbq[2*CH + c*32 + d0], b1 = sbq[2*CH + c*32 + d0 + 1];
                __half* vb = svt + (c*32 + d0)*VTS;
                vb[r0]           = __float2half_rn(acc[j][0] + b0);
                vb[VTS + r0]     = __float2half_rn(acc[j][1] + b1);
                vb[r0 + 8]       = __float2half_rn(acc[j][2] + b0);
                vb[VTS + r0 + 8] = __float2half_rn(acc[j][3] + b1);
            }
        }
    }
    __syncthreads();

    // ================= phase 2: attention, 24 warp-tasks, 2 per warp =========
    #pragma unroll 1
    for (int rep = 0; rep < 2; ++rep) {
        const int task = warp + 12*rep;       // 0..23
        const int h    = task >> 2;
        const int sm0  = (task & 3) * 16;

        // scores m16 x n64, K=32
        float acc[8][4];
        #pragma unroll
        for (int j = 0; j < 8; ++j)
            #pragma unroll
            for (int i = 0; i < 4; ++i) acc[j][i] = 0.f;

        const __half* aq = sq + (sm0 + g)*SXS + h*HDIM + 2*lc;
        #pragma unroll
        for (int kk = 0; kk < 2; ++kk) {
            const int k0 = kk * 16;
            unsigned a[4];
            a[0] = ldu(aq + k0);       a[1] = ldu(aq + 8*SXS + k0);
            a[2] = ldu(aq + k0 + 8);   a[3] = ldu(aq + 8*SXS + k0 + 8);
            #pragma unroll
            for (int j = 0; j < 8; ++j) {
                const __half* bkp = sk + (8*j + g)*SXS + h*HDIM + 2*lc + k0;
                mma16(acc[j], a, ldu(bkp), ldu(bkp + 8));
            }
        }

        // + bias (L2-resident LDG), register softmax
        const float* bp = bias + h*4096 + (sm0 + g)*64 + 2*lc;
        float mx0 = -1e30f, mx1 = -1e30f;
        #pragma unroll
        for (int j = 0; j < 8; ++j) {
            const float2 bA = *(const float2*)(bp + 8*j);
            const float2 bB = *(const float2*)(bp + 512 + 8*j);
            acc[j][0] += bA.x; acc[j][1] += bA.y;
            acc[j][2] += bB.x; acc[j][3] += bB.y;
            mx0 = fmaxf(mx0, fmaxf(acc[j][0], acc[j][1]));
            mx1 = fmaxf(mx1, fmaxf(acc[j][2], acc[j][3]));
        }
        mx0 = fmaxf(mx0, __shfl_xor_sync(0xffffffffu, mx0, 1));
        mx0 = fmaxf(mx0, __shfl_xor_sync(0xffffffffu, mx0, 2));
        mx1 = fmaxf(mx1, __shfl_xor_sync(0xffffffffu, mx1, 1));
        mx1 = fmaxf(mx1, __shfl_xor_sync(0xffffffffu, mx1, 2));
        float s0 = 0.f, s1 = 0.f;
        #pragma unroll
        for (int j = 0; j < 8; ++j) {
            acc[j][0] = __expf(acc[j][0] - mx0); acc[j][1] = __expf(acc[j][1] - mx0);
            acc[j][2] = __expf(acc[j][2] - mx1); acc[j][3] = __expf(acc[j][3] - mx1);
            s0 += acc[j][0] + acc[j][1];
            s1 += acc[j][2] + acc[j][3];
        }
        s0 += __shfl_xor_sync(0xffffffffu, s0, 1);
        s0 += __shfl_xor_sync(0xffffffffu, s0, 2);
        s1 += __shfl_xor_sync(0xffffffffu, s1, 1);
        s1 += __shfl_xor_sync(0xffffffffu, s1, 2);
        const float inv0 = 1.0f / s0, inv1 = 1.0f / s1;

        // pack probs: D-fragment layout == A-fragment layout for P@V
        unsigned pa[8], pb[8];
        #pragma unroll
        for (int j = 0; j < 8; ++j) {
            pa[j] = pk(acc[j][0]*inv0, acc[j][1]*inv0);
            pb[j] = pk(acc[j][2]*inv1, acc[j][3]*inv1);
        }

        // out_h m16 x n32, K=64; B = v^T
        float oacc[4][4];
        #pragma unroll
        for (int j = 0; j < 4; ++j)
            #pragma unroll
            for (int i = 0; i < 4; ++i) oacc[j][i] = 0.f;
        #pragma unroll
        for (int kk = 0; kk < 4; ++kk) {
            unsigned a[4] = { pa[2*kk], pb[2*kk], pa[2*kk+1], pb[2*kk+1] };
            #pragma unroll
            for (int jj = 0; jj < 4; ++jj) {
                const __half* bvp = svt + (h*HDIM + 8*jj + g)*VTS + 2*lc + 16*kk;
                mma16(oacc[jj], a, ldu(bvp), ldu(bvp + 8));
            }
        }

        // write attention output into sx (cols h*32..)
        __half* so = sx + (sm0 + g)*SXS + h*HDIM;
        #pragma unroll
        for (int jj = 0; jj < 4; ++jj) {
            const int cc = 8*jj + 2*lc;
            *(unsigned*)(so + cc)         = pk(oacc[jj][0], oacc[jj][1]);
            *(unsigned*)(so + 8*SXS + cc) = pk(oacc[jj][2], oacc[jj][3]);
        }
    }
    __syncthreads();

    // ================= phase 3: projection, direct global store ==============
    #pragma unroll 1
    for (int chunk = 0; chunk < 2; ++chunk) {
        const uint2* wfb = d_proj_wf + ((chunk*12 + nwt*4)*12)*32 + lane;
        float acc[4][4];
        #pragma unroll
        for (int j = 0; j < 4; ++j)
            #pragma unroll
            for (int i = 0; i < 4; ++i) acc[j][i] = 0.f;

        const __half* a0 = sx + (m0 + g)*SXS + 2*lc;   // attention output
        #pragma unroll 2
        for (int ks = 0; ks < 12; ++ks) {
            const int k0 = ks * 16;
            unsigned a[4];
            a[0] = ldu(a0 + k0);       a[1] = ldu(a0 + 8*SXS + k0);
            a[2] = ldu(a0 + k0 + 8);   a[3] = ldu(a0 + 8*SXS + k0 + 8);
            #pragma unroll
            for (int j = 0; j < 4; ++j) {
                const uint2 bb = __ldg(wfb + (j*12 + ks)*32);
                mma16(acc[j], a, bb.x, bb.y);
            }
        }

        const int t0 = m0 + g;
        const int t1 = t0 + 8;
        const long long ga0 = base + (long long)(t0 >> 3) * (IMGW*CH) + (t0 & 7) * CH;
        const long long ga1 = base + (long long)(t1 >> 3) * (IMGW*CH) + (t1 & 7) * CH;
        #pragma unroll
        for (int j = 0; j < 4; ++j) {
            const int n = chunk*96 + nwt*32 + 8*j + 2*lc;
            const float b0 = sbp[n], b1 = sbp[n + 1];
            *(float2*)(out + ga0 + n) = make_float2(acc[j][0] + b0, acc[j][1] + b1);
            *(float2*)(out + ga1 + n) = make_float2(acc[j][2] + b0, acc[j][3] + b1);
        }
    }
}

extern "C" void kernel_launch(void* const* d_in, const int* in_sizes, int n_in,
                              void* d_out, int out_size)
{
    const float* x      = (const float*)d_in[0];
    const float* qkv_w  = (const float*)d_in[1];
    const float* qkv_b  = (const float*)d_in[2];
    const float* proj_w = (const float*)d_in[3];
    const float* proj_b = (const float*)d_in[4];
    const float* bias   = (const float*)d_in[5];
    float* out = (float*)d_out;

    cudaFuncSetAttribute(win_attn_kernel,
                         cudaFuncAttributeMaxDynamicSharedMemorySize, SMEM_BYTES);

    prep_weights<<<(QKV_FRAGS + PROJ_FRAGS + 255) / 256, 256>>>(qkv_w, proj_w);

    const int n_windows = BATCH * (IMGH/8) * (IMGW/8);   // 4096
    win_attn_kernel<<<n_windows, 384, SMEM_BYTES>>>(x, qkv_b, proj_b, bias, out);
}